// round 4
// baseline (speedup 1.0000x reference)
#include <cuda_runtime.h>
#include <cstdint>
#include <cstddef>

// Problem constants
#define NE 8
#define NC 4096
#define NM 1024
#define NH 4096
#define NO 1024

// Intermediate h = relu(x@W1^T+b1): [E, C, H] fp32 (512 MB scratch, no alloc allowed)
__device__ float g_hbuf[(size_t)NE * NC * NH];

__device__ __forceinline__ uint32_t f2tf32(float f) {
    uint32_t u;
    asm("cvt.rna.tf32.f32 %0, %1;" : "=r"(u) : "f"(f));
    return u;
}

// D[row, col] = sum_k A[row,k] * B(k,col)  (+ bias[col], optional ReLU)
// A: row-major [4096 x K], lda = K
// B_KMAJOR=true : B(k,n) = Bg[n*K + n? no -> n*K + k]   (weights stored [N,K] row-major; GEMM1)
// B_KMAJOR=false: B(k,n) = Bg[k*Ntot + n]               (weights stored [K,N] row-major; GEMM2)
//
// CTA tile 128x128, K-step 32. 8 warps in 2(m) x 4(n) grid, warp tile 64x32.
// mma.sync.aligned.m16n8k8 tf32: per warp 4(m-tiles) x 4(n-tiles).
template <bool B_KMAJOR, bool RELU>
__global__ __launch_bounds__(256, 2)
void ffn_gemm_tf32(const float* __restrict__ Ag, const float* __restrict__ Bg,
                   const float* __restrict__ biasg, float* __restrict__ Dg,
                   int K, int Ntot,
                   size_t sA, size_t sB, size_t sBias, size_t sD)
{
    const int tid  = threadIdx.x;
    const int lane = tid & 31;
    const int warp = tid >> 5;
    const int wm   = warp >> 2;   // 0..1  -> m offset wm*64
    const int wn   = warp & 3;    // 0..3  -> n offset wn*32
    const int u    = lane >> 2;   // 0..7
    const int v    = lane & 3;    // 0..3

    const int e  = blockIdx.z;
    const int mb = blockIdx.y * 128;
    const int nb = blockIdx.x * 128;

    const float* A    = Ag    + (size_t)e * sA;
    const float* B    = Bg    + (size_t)e * sB;
    const float* bias = biasg + (size_t)e * sBias;
    float*       D    = Dg    + (size_t)e * sD;

    // As: [m=128][k=32] stride 36  (pad -> frag LDS bank = lane + const: conflict-free)
    // Bs kmajor  : [n=128][k=32] stride 36  (same property)
    // Bs rowmajor: [k=32][n=128] stride 136 (bank = 8v+u bijective: conflict-free)
    __shared__ uint32_t As[128 * 36];
    __shared__ uint32_t Bs[128 * 36];   // 128*36=4608 >= 32*136=4352

    float acc[4][4][4];
    #pragma unroll
    for (int a = 0; a < 4; a++)
        #pragma unroll
        for (int b = 0; b < 4; b++)
            #pragma unroll
            for (int c = 0; c < 4; c++)
                acc[a][b][c] = 0.0f;

    // Global->smem thread mapping (256 threads, 4 float4 each per tile)
    const int r0  = tid >> 3;          // 0..31 (row within 32-row slab; rows = i*32 + r0)
    const int c4  = (tid & 7) << 2;    // 0,4,...,28 (k offset within 32)
    const int kb0 = tid >> 5;          // 0..7  (rowmajor-B: k row = i*8 + kb0)
    const int n4  = (tid & 31) << 2;   // 0..124 (rowmajor-B: n offset)

    for (int k0 = 0; k0 < K; k0 += 32) {
        float4 aR[4], bR[4];
        #pragma unroll
        for (int i = 0; i < 4; i++)
            aR[i] = *(const float4*)(A + (size_t)(mb + i * 32 + r0) * K + k0 + c4);
        if (B_KMAJOR) {
            #pragma unroll
            for (int i = 0; i < 4; i++)
                bR[i] = *(const float4*)(B + (size_t)(nb + i * 32 + r0) * K + k0 + c4);
        } else {
            #pragma unroll
            for (int i = 0; i < 4; i++)
                bR[i] = *(const float4*)(B + (size_t)(k0 + i * 8 + kb0) * Ntot + nb + n4);
        }

        __syncthreads();   // previous iteration's compute done reading smem

        #pragma unroll
        for (int i = 0; i < 4; i++) {
            uint4 t;
            t.x = f2tf32(aR[i].x); t.y = f2tf32(aR[i].y);
            t.z = f2tf32(aR[i].z); t.w = f2tf32(aR[i].w);
            *(uint4*)&As[(i * 32 + r0) * 36 + c4] = t;
        }
        #pragma unroll
        for (int i = 0; i < 4; i++) {
            uint4 t;
            t.x = f2tf32(bR[i].x); t.y = f2tf32(bR[i].y);
            t.z = f2tf32(bR[i].z); t.w = f2tf32(bR[i].w);
            if (B_KMAJOR)
                *(uint4*)&Bs[(i * 32 + r0) * 36 + c4] = t;
            else
                *(uint4*)&Bs[(i * 8 + kb0) * 136 + n4] = t;
        }

        __syncthreads();   // tile visible

        #pragma unroll
        for (int kk = 0; kk < 32; kk += 8) {
            uint32_t af[4][4];
            uint32_t bf[4][2];
            #pragma unroll
            for (int tm = 0; tm < 4; tm++) {
                const int ia = (wm * 64 + tm * 16 + u) * 36 + kk + v;
                af[tm][0] = As[ia];
                af[tm][1] = As[ia + 8 * 36];
                af[tm][2] = As[ia + 4];
                af[tm][3] = As[ia + 8 * 36 + 4];
            }
            #pragma unroll
            for (int tn = 0; tn < 4; tn++) {
                const int nn = wn * 32 + tn * 8 + u;
                if (B_KMAJOR) {
                    const int ib = nn * 36 + kk + v;
                    bf[tn][0] = Bs[ib];
                    bf[tn][1] = Bs[ib + 4];
                } else {
                    const int ib = (kk + v) * 136 + nn;
                    bf[tn][0] = Bs[ib];
                    bf[tn][1] = Bs[ib + 4 * 136];
                }
            }
            #pragma unroll
            for (int tm = 0; tm < 4; tm++)
                #pragma unroll
                for (int tn = 0; tn < 4; tn++) {
                    float* c = acc[tm][tn];
                    asm volatile(
                        "mma.sync.aligned.m16n8k8.row.col.f32.tf32.tf32.f32 "
                        "{%0,%1,%2,%3}, {%4,%5,%6,%7}, {%8,%9}, {%0,%1,%2,%3};\n"
                        : "+f"(c[0]), "+f"(c[1]), "+f"(c[2]), "+f"(c[3])
                        : "r"(af[tm][0]), "r"(af[tm][1]), "r"(af[tm][2]), "r"(af[tm][3]),
                          "r"(bf[tn][0]), "r"(bf[tn][1]));
                }
        }
    }

    // Epilogue: bias (+ReLU), fp32 out
    #pragma unroll
    for (int tm = 0; tm < 4; tm++) {
        const int row = mb + wm * 64 + tm * 16 + u;
        #pragma unroll
        for (int tn = 0; tn < 4; tn++) {
            const int col = nb + wn * 32 + tn * 8 + 2 * v;
            const float2 bv = *(const float2*)&bias[col];
            float x0 = acc[tm][tn][0] + bv.x;
            float x1 = acc[tm][tn][1] + bv.y;
            float x2 = acc[tm][tn][2] + bv.x;
            float x3 = acc[tm][tn][3] + bv.y;
            if (RELU) {
                x0 = fmaxf(x0, 0.0f); x1 = fmaxf(x1, 0.0f);
                x2 = fmaxf(x2, 0.0f); x3 = fmaxf(x3, 0.0f);
            }
            float2 o0 = make_float2(x0, x1);
            float2 o1 = make_float2(x2, x3);
            *(float2*)&D[(size_t)row * Ntot + col]       = o0;
            *(float2*)&D[(size_t)(row + 8) * Ntot + col] = o1;
        }
    }
}

extern "C" void kernel_launch(void* const* d_in, const int* in_sizes, int n_in,
                              void* d_out, int out_size)
{
    const float* x     = (const float*)d_in[0];   // [E, C, M]
    const float* fc1_w = (const float*)d_in[1];   // [E, H, M]
    const float* fc1_b = (const float*)d_in[2];   // [E, H]
    const float* fc2_w = (const float*)d_in[3];   // [E, H, O]
    const float* fc2_b = (const float*)d_in[4];   // [E, O]
    float* out = (float*)d_out;                   // [E, C, O]

    float* hb = nullptr;
    cudaGetSymbolAddress((void**)&hb, g_hbuf);

    // GEMM1: h[e] = relu(x[e] @ fc1_w[e]^T + b1[e])   (M-rows=C, N=H, K=M, B k-major)
    dim3 g1(NH / 128, NC / 128, NE);
    ffn_gemm_tf32<true, true><<<g1, 256>>>(
        x, fc1_w, fc1_b, hb,
        NM, NH,
        (size_t)NC * NM, (size_t)NH * NM, (size_t)NH, (size_t)NC * NH);

    // GEMM2: y[e] = h[e] @ fc2_w[e] + b2[e]           (M-rows=C, N=O, K=H, B row-major)
    dim3 g2(NO / 128, NC / 128, NE);
    ffn_gemm_tf32<false, false><<<g2, 256>>>(
        hb, fc2_w, fc2_b, out,
        NH, NO,
        (size_t)NC * NH, (size_t)NH * NO, (size_t)NO, (size_t)NC * NO);
}